// round 1
// baseline (speedup 1.0000x reference)
#include <cuda_runtime.h>
#include <cstdint>

// SemiConv2d: 5x5 max-plus dilation, 'same' padding with -inf.
// input:  (16, 64, 256, 256) fp32  -> 1024 independent 256x256 images
// kernel: (5, 5) fp32
// out[i,j] = max_{u,v} x[i+u-2, j+v-2] + k[u,v]
//
// Strategy: row-streaming with 5 rotating accumulators per output column.
// Each thread handles 4 adjacent output columns (float4 I/O) over a 64-row
// strip. Per input row it applies one kernel row to each of 5 pending
// outputs (25 FADD + ~24 FMNMX per output, the theoretical minimum), and
// completes/stores exactly one output row per step. Borders are handled by
// per-float4 predicated loads substituting -inf (each 16B block is either
// fully valid or fully out-of-range in columns).

#define IMG_H 256
#define IMG_W 256

__global__ void __launch_bounds__(128) dil5x5_kernel(
    const float* __restrict__ x,
    const float* __restrict__ kw,
    float* __restrict__ out)
{
    const int lane   = threadIdx.x & 31;
    const int wlocal = threadIdx.x >> 5;
    const int w      = blockIdx.x * 4 + wlocal;   // global warp-task id, 0..8191

    const int img   = w >> 3;          // 0..1023
    const int strip = (w >> 1) & 3;    // 0..3  -> 64-row strip
    const int half  = w & 1;           // 0..1  -> 128-col half

    const int i0 = strip << 6;                    // first output row of strip
    const int j0 = (half << 7) + (lane << 2);     // first of 4 output cols

    // Kernel weights in registers (uniform across threads, L1-broadcast load)
    float k[25];
#pragma unroll
    for (int t = 0; t < 25; ++t) k[t] = kw[t];

    const float NI = __int_as_float(0xff800000u); // -inf

    // 5 rotating accumulators x 4 columns
    float acc[5][4];
#pragma unroll
    for (int q = 0; q < 5; ++q)
#pragma unroll
        for (int c = 0; c < 4; ++c) acc[q][c] = NI;

    const float* xim = x   + (size_t)img * (IMG_H * IMG_W);
    float*       oim = out + (size_t)img * (IMG_H * IMG_W);

    // Column-block validity (16B blocks at j0-4, j0, j0+4).
    // Needed columns are j0-2 .. j0+5 -> uses X[2..9].
    // Block0 (cols j0-4..j0-1) invalid iff j0==0 (we only use cols j0-2,j0-1).
    // Block1 (cols j0..j0+3) always valid.
    // Block2 (cols j0+4..j0+7) invalid iff j0==252 (we only use j0+4,j0+5).
    const bool c0ok = (j0 != 0);
    const bool c2ok = (j0 != 252);

    // Steps s = 0..69 process input row r = i0 + s - 2.
    // Output row i = i0 + s - 4 completes at step s (stored for s in [4,67]).
    for (int sb = 0; sb < 70; sb += 5) {
#pragma unroll
        for (int ph = 0; ph < 5; ++ph) {
            const int s = sb + ph;
            const int r = i0 + s - 2;
            const bool rok = (r >= 0) && (r < IMG_H);
            const float* row = xim + r * IMG_W + (j0 - 4);

            const float4 NIV = make_float4(NI, NI, NI, NI);
            float4 A = (rok && c0ok) ? *(const float4*)(row)     : NIV;
            float4 B = (rok)         ? *(const float4*)(row + 4) : NIV;
            float4 C = (rok && c2ok) ? *(const float4*)(row + 8) : NIV;

            // X[m] = column j0 - 4 + m ; tap column j0+c+v-2 -> X[c+v+2]
            float X[12] = {A.x, A.y, A.z, A.w,
                           B.x, B.y, B.z, B.w,
                           C.x, C.y, C.z, C.w};

#pragma unroll
            for (int q = 0; q < 5; ++q) {
                const int d = (q - ph + 5) % 5;   // compile-time
                const int u = 4 - d;              // kernel row for this slot
                if (d == 4) {
                    // freshly started output: initialize with first tap
#pragma unroll
                    for (int c = 0; c < 4; ++c)
                        acc[q][c] = X[c + 2] + k[u * 5 + 0];
#pragma unroll
                    for (int v = 1; v < 5; ++v)
#pragma unroll
                        for (int c = 0; c < 4; ++c)
                            acc[q][c] = fmaxf(acc[q][c], X[c + v + 2] + k[u * 5 + v]);
                } else {
#pragma unroll
                    for (int v = 0; v < 5; ++v)
#pragma unroll
                        for (int c = 0; c < 4; ++c)
                            acc[q][c] = fmaxf(acc[q][c], X[c + v + 2] + k[u * 5 + v]);
                }
            }

            // Slot q == ph just received its last kernel row (u==4): emit.
            if (s >= 4 && s <= 67) {
                float4 o = make_float4(acc[ph][0], acc[ph][1], acc[ph][2], acc[ph][3]);
                *(float4*)(oim + (size_t)(i0 + s - 4) * IMG_W + j0) = o;
            }
            // No explicit reset: slot ph is re-initialized on its d==4 phase
            // (next step) before any further use.
        }
    }
}

extern "C" void kernel_launch(void* const* d_in, const int* in_sizes, int n_in,
                              void* d_out, int out_size) {
    const float* x  = (const float*)d_in[0];  // (16,64,256,256)
    const float* kw = (const float*)d_in[1];  // (5,5)
    float* out = (float*)d_out;
    // 8192 warp-tasks = 1024 images x 4 row-strips x 2 column-halves
    dil5x5_kernel<<<2048, 128>>>(x, kw, out);
}

// round 4
// speedup vs baseline: 1.0749x; 1.0749x over previous
#include <cuda_runtime.h>
#include <cstdint>

// SemiConv2d: 5x5 max-plus dilation, 'same' padding with -inf.
// input:  (16, 64, 256, 256) fp32 -> 1024 independent 256x256 images
// kernel: (5, 5) fp32
//
// Row-streaming, 5 rotating accumulator slots, 4 cols/thread (float4 I/O).
// Overhead-minimized vs R1:
//  - invalid rows (above/below image) are read from a tiny -inf scratch row
//    selected by ONE 64-bit pointer select (2 instrs) instead of 12 FSELs
//  - column-halo loads A/C are predicated on LOOP-INVARIANT predicates with
//    the destination registers pre-set to -inf once before the loop
//  - 68 steps (exact) instead of 70 (no ghost work)

#define IMG_H 256
#define IMG_W 256

__device__ __align__(16) float g_ninf[16];

__global__ void fill_ninf_kernel() {
    g_ninf[threadIdx.x] = __int_as_float(0xff800000u);
}

__global__ void __launch_bounds__(128) dil5x5_kernel(
    const float* __restrict__ x,
    const float* __restrict__ kw,
    float* __restrict__ out)
{
    const int lane   = threadIdx.x & 31;
    const int wlocal = threadIdx.x >> 5;
    const int w      = blockIdx.x * 4 + wlocal;   // warp-task id, 0..8191

    const int img   = w >> 3;          // 0..1023
    const int strip = (w >> 1) & 3;    // 0..3  -> 64-row strip
    const int half  = w & 1;           // 0..1  -> 128-col half

    const int i0 = strip << 6;
    const int j0 = (half << 7) + (lane << 2);

    float k[25];
#pragma unroll
    for (int t = 0; t < 25; ++t) k[t] = kw[t];

    const float NI = __int_as_float(0xff800000u);

    float acc[5][4];
#pragma unroll
    for (int q = 0; q < 5; ++q)
#pragma unroll
        for (int c = 0; c < 4; ++c) acc[q][c] = NI;

    const float* xim = x   + (size_t)img * (IMG_H * IMG_W);
    float*       oim = out + (size_t)img * (IMG_H * IMG_W);

    // Loop-invariant column-halo validity. A covers cols j0-4..j0-1 (we use
    // j0-2,j0-1): invalid only when j0==0. C covers j0+4..j0+7 (we use
    // j0+4,j0+5): invalid only when j0==252. B (j0..j0+3) always valid.
    const bool c0ok = (j0 != 0);
    const bool c2ok = (j0 != 252);

    const float4 NIV = make_float4(NI, NI, NI, NI);
    float4 A = NIV, B = NIV, C = NIV;   // A/C stay -inf forever on edge lanes

    const float* ninf = g_ninf;         // 16 floats of -inf

    int r = i0 - 2;                                         // input row
    const float* rowptr = xim + (ptrdiff_t)r * IMG_W + (j0 - 4);
    float* optr = oim + (size_t)i0 * IMG_W + j0;

    // Step s (0..67): consume input row r = i0+s-2 (or -inf row if outside
    // the image), emit output row r-2 = i0+s-4 once s>=4.
#define DO_STEP(PH)                                                          \
    {                                                                        \
        const bool vok = ((unsigned)r) < (unsigned)IMG_H;                    \
        const float* rp = vok ? rowptr : ninf;                               \
        if (c0ok) A = *(const float4*)(rp);                                  \
        B = *(const float4*)(rp + 4);                                        \
        if (c2ok) C = *(const float4*)(rp + 8);                              \
        float X[12] = {A.x, A.y, A.z, A.w,                                   \
                       B.x, B.y, B.z, B.w,                                   \
                       C.x, C.y, C.z, C.w};                                  \
        _Pragma("unroll")                                                    \
        for (int q = 0; q < 5; ++q) {                                        \
            const int d = (q - (PH) + 5) % 5;   /* compile-time */           \
            const int u = 4 - d;                /* kernel row   */           \
            if (d == 4) {                                                    \
                _Pragma("unroll")                                            \
                for (int c = 0; c < 4; ++c)                                  \
                    acc[q][c] = X[c + 2] + k[u * 5 + 0];                     \
                _Pragma("unroll")                                            \
                for (int v = 1; v < 5; ++v)                                  \
                    _Pragma("unroll")                                        \
                    for (int c = 0; c < 4; ++c)                              \
                        acc[q][c] = fmaxf(acc[q][c], X[c + v + 2] + k[u * 5 + v]); \
            } else {                                                         \
                _Pragma("unroll")                                            \
                for (int v = 0; v < 5; ++v)                                  \
                    _Pragma("unroll")                                        \
                    for (int c = 0; c < 4; ++c)                              \
                        acc[q][c] = fmaxf(acc[q][c], X[c + v + 2] + k[u * 5 + v]); \
            }                                                                \
        }                                                                    \
        if (r >= i0 + 2) {                                                   \
            *(float4*)optr = make_float4(acc[PH][0], acc[PH][1],             \
                                         acc[PH][2], acc[PH][3]);            \
            optr += IMG_W;                                                   \
        }                                                                    \
        ++r;                                                                 \
        rowptr += IMG_W;                                                     \
    }

    for (int sb = 0; sb < 13; ++sb) {
        DO_STEP(0) DO_STEP(1) DO_STEP(2) DO_STEP(3) DO_STEP(4)
    }
    // steps 65, 66, 67 (phases 0,1,2) finish the last outputs
    DO_STEP(0) DO_STEP(1) DO_STEP(2)
#undef DO_STEP
}

extern "C" void kernel_launch(void* const* d_in, const int* in_sizes, int n_in,
                              void* d_out, int out_size) {
    const float* x  = (const float*)d_in[0];  // (16,64,256,256)
    const float* kw = (const float*)d_in[1];  // (5,5)
    float* out = (float*)d_out;
    fill_ninf_kernel<<<1, 16>>>();
    dil5x5_kernel<<<2048, 128>>>(x, kw, out);
}